// round 4
// baseline (speedup 1.0000x reference)
#include <cuda_runtime.h>

#define BB 32
#define NN 256
#define NF 16
#define NL 3
#define NODES (BB*NN)
#define WPB 4   // warps (dst nodes) per block

// ping-pong state + per-layer precomputed node terms (static device allocs: allowed)
__device__ float4 g_x[2][NODES];
__device__ float  g_h[2][NODES*NF];
__device__ float  g_A[NODES*NF];    // h_i @ We1[0:NF]           (src half)
__device__ float  g_Bjb[NODES*NF];  // h_j @ We1[NF:2NF] + be1   (dst half, bias folded)
__device__ float  g_hWh[NODES*NF];  // h_j @ Wh1[0:NF] + bh1     (node-update h half)
__device__ float  g_hv[NODES];      // h_j @ W_v                 (velocity gate scalar)

__global__ void init_kernel(const float* __restrict__ xs,
                            const float* __restrict__ charges,
                            const float* __restrict__ W_in,
                            const float* __restrict__ b_in) {
    int node = blockIdx.x * blockDim.x + threadIdx.x;
    if (node >= NODES) return;
    float c = charges[node];
    #pragma unroll
    for (int k = 0; k < NF; k++) {
        float v = fmaf(c, W_in[k], b_in[k]);
        g_h[0][node*NF + k] = v > 0.f ? v : 0.f;
    }
    float4 x;
    x.x = xs[node*3 + 0];
    x.y = xs[node*3 + 1];
    x.z = xs[node*3 + 2];
    x.w = 0.f;
    g_x[0][node] = x;
}

__global__ void precompute_kernel(int l, int cur,
                                  const float* __restrict__ We1,
                                  const float* __restrict__ be1,
                                  const float* __restrict__ Wh1,
                                  const float* __restrict__ bh1,
                                  const float* __restrict__ W_v) {
    int gid = blockIdx.x * blockDim.x + threadIdx.x;
    int node = gid >> 4;
    int k = gid & 15;
    if (node >= NODES) return;
    const float* h   = &g_h[cur][node*NF];
    const float* we1 = We1 + l * (2*NF + 1) * NF;
    const float* wh1 = Wh1 + l * (2*NF) * NF;
    float hh[NF];
    #pragma unroll
    for (int f = 0; f < NF; f++) hh[f] = h[f];
    float a = 0.f, bb = 0.f, hw = 0.f;
    #pragma unroll
    for (int f = 0; f < NF; f++) {
        a  = fmaf(hh[f], we1[f*NF + k],        a);
        bb = fmaf(hh[f], we1[(NF+f)*NF + k],   bb);
        hw = fmaf(hh[f], wh1[f*NF + k],        hw);
    }
    g_A[node*NF + k]   = a;
    g_Bjb[node*NF + k] = bb + be1[l*NF + k];
    g_hWh[node*NF + k] = hw + bh1[l*NF + k];
    if (k == 0) {
        float hv = 0.f;
        #pragma unroll
        for (int f = 0; f < NF; f++) hv = fmaf(hh[f], W_v[l*NF + f], hv);
        g_hv[node] = hv;
    }
}

__global__ void __launch_bounds__(WPB*32)
edge_kernel(int l, int cur, int nxt, int last,
            const float* __restrict__ We1,
            const float* __restrict__ We2,
            const float* __restrict__ be2,
            const float* __restrict__ Wx,
            const float* __restrict__ Wh1,
            const float* __restrict__ vs,
            float* __restrict__ out) {
    __shared__ float  sA[NN*17];     // padded rows: conflict-free per-lane LDS
    __shared__ float4 sX[NN];
    __shared__ float4 sWe2[NF*4];    // row f -> 4x float4 (broadcast reads)
    __shared__ float  sWh1b[NF*NF];  // Wh1 m_agg half: [f][k]

    int tid  = threadIdx.x;
    int lane = tid & 31;
    int warp = tid >> 5;
    int b     = blockIdx.x / (NN/WPB);
    int jbase = (blockIdx.x % (NN/WPB)) * WPB;
    int nbase = b * NN;

    // cooperative tile loads
    for (int idx = tid; idx < NN*NF; idx += WPB*32) {
        int i = idx >> 4, k = idx & 15;
        sA[i*17 + k] = g_A[(nbase + i)*NF + k];
    }
    for (int i = tid; i < NN; i += WPB*32) sX[i] = g_x[cur][nbase + i];
    {
        const float4* we2v = reinterpret_cast<const float4*>(We2 + l*NF*NF);
        if (tid < NF*4) sWe2[tid] = we2v[tid];
    }
    for (int idx = tid; idx < NF*NF; idx += WPB*32) {
        int f = idx >> 4, k = idx & 15;
        sWh1b[idx] = Wh1[l*(2*NF)*NF + (NF + f)*NF + k];
    }
    __syncthreads();

    int j = jbase + warp;
    int node = nbase + j;

    // per-warp constants in registers
    float Bjb[NF], wr[NF], wxv[NF], bev[NF];
    const float* wrp = We1 + l*(2*NF+1)*NF + (2*NF)*NF;  // r2 row of We1
    #pragma unroll
    for (int k = 0; k < NF; k++) {
        Bjb[k] = g_Bjb[node*NF + k];
        wr[k]  = wrp[k];
        wxv[k] = Wx[l*NF + k];
        bev[k] = be2[l*NF + k];
    }
    float4 xj = sX[j];

    float magg[NF];
    #pragma unroll
    for (int k = 0; k < NF; k++) magg[k] = 0.f;
    float ax = 0.f, ay = 0.f, az = 0.f;

    for (int it = 0; it < NN/32; it++) {
        int i = it*32 + lane;
        float mask = (i == j) ? 0.f : 1.f;
        float4 xi = sX[i];
        float dx = xj.x - xi.x;
        float dy = xj.y - xi.y;
        float dz = xj.z - xi.z;
        float r2 = fmaf(dx, dx, fmaf(dy, dy, dz*dz));

        float t[NF];
        #pragma unroll
        for (int k = 0; k < NF; k++) {
            float v = fmaf(r2, wr[k], sA[i*17 + k] + Bjb[k]);
            t[k] = v > 0.f ? v : 0.f;
        }

        float m[NF];
        #pragma unroll
        for (int k = 0; k < NF; k++) m[k] = bev[k];
        #pragma unroll
        for (int f = 0; f < NF; f++) {
            float tf = t[f];
            float4 w0 = sWe2[f*4 + 0];
            float4 w1 = sWe2[f*4 + 1];
            float4 w2 = sWe2[f*4 + 2];
            float4 w3 = sWe2[f*4 + 3];
            m[0]  = fmaf(tf, w0.x, m[0]);   m[1]  = fmaf(tf, w0.y, m[1]);
            m[2]  = fmaf(tf, w0.z, m[2]);   m[3]  = fmaf(tf, w0.w, m[3]);
            m[4]  = fmaf(tf, w1.x, m[4]);   m[5]  = fmaf(tf, w1.y, m[5]);
            m[6]  = fmaf(tf, w1.z, m[6]);   m[7]  = fmaf(tf, w1.w, m[7]);
            m[8]  = fmaf(tf, w2.x, m[8]);   m[9]  = fmaf(tf, w2.y, m[9]);
            m[10] = fmaf(tf, w2.z, m[10]);  m[11] = fmaf(tf, w2.w, m[11]);
            m[12] = fmaf(tf, w3.x, m[12]);  m[13] = fmaf(tf, w3.y, m[13]);
            m[14] = fmaf(tf, w3.z, m[14]);  m[15] = fmaf(tf, w3.w, m[15]);
        }

        float w0s = 0.f, w1s = 0.f;
        #pragma unroll
        for (int k = 0; k < NF; k++) {
            float mk = m[k] > 0.f ? m[k] : 0.f;
            if (k & 1) w1s = fmaf(mk, wxv[k], w1s);
            else       w0s = fmaf(mk, wxv[k], w0s);
            magg[k] = fmaf(mk, mask, magg[k]);
        }
        float w = (w0s + w1s) * mask;
        ax = fmaf(dx, w, ax);
        ay = fmaf(dy, w, ay);
        az = fmaf(dz, w, az);
    }

    // warp butterfly reductions (all lanes end with full sums)
    #pragma unroll
    for (int k = 0; k < NF; k++) {
        #pragma unroll
        for (int off = 16; off; off >>= 1)
            magg[k] += __shfl_xor_sync(0xffffffffu, magg[k], off);
    }
    #pragma unroll
    for (int off = 16; off; off >>= 1) {
        ax += __shfl_xor_sync(0xffffffffu, ax, off);
        ay += __shfl_xor_sync(0xffffffffu, ay, off);
        az += __shfl_xor_sync(0xffffffffu, az, off);
    }

    if (lane == 0) {
        float hv = g_hv[node];
        const float inv = 1.f / (NN - 1);
        float ox = xj.x + ax*inv + vs[node*3 + 0]*hv;
        float oy = xj.y + ay*inv + vs[node*3 + 1]*hv;
        float oz = xj.z + az*inv + vs[node*3 + 2]*hv;
        if (last) {
            out[node*3 + 0] = ox;
            out[node*3 + 1] = oy;
            out[node*3 + 2] = oz;
        } else {
            g_x[nxt][node] = make_float4(ox, oy, oz, 0.f);
        }
    }
    if (!last && lane < NF) {
        float g = g_hWh[node*NF + lane];
        #pragma unroll
        for (int f = 0; f < NF; f++) g = fmaf(magg[f], sWh1b[f*NF + lane], g);
        float r = g > 0.f ? g : 0.f;
        g_h[nxt][node*NF + lane] = g_h[cur][node*NF + lane] + r;
    }
}

extern "C" void kernel_launch(void* const* d_in, const int* in_sizes, int n_in,
                              void* d_out, int out_size) {
    const float* xs      = (const float*)d_in[0];
    const float* vs      = (const float*)d_in[1];
    const float* charges = (const float*)d_in[2];
    const float* W_in    = (const float*)d_in[3];
    const float* b_in    = (const float*)d_in[4];
    const float* W_v     = (const float*)d_in[5];
    const float* We1     = (const float*)d_in[6];
    const float* be1     = (const float*)d_in[7];
    const float* We2     = (const float*)d_in[8];
    const float* be2     = (const float*)d_in[9];
    const float* Wx      = (const float*)d_in[10];
    const float* Wh1     = (const float*)d_in[11];
    const float* bh1     = (const float*)d_in[12];
    float* out = (float*)d_out;

    init_kernel<<<(NODES + 255)/256, 256>>>(xs, charges, W_in, b_in);

    int cur = 0;
    for (int l = 0; l < NL; l++) {
        precompute_kernel<<<(NODES*NF + 255)/256, 256>>>(l, cur, We1, be1, Wh1, bh1, W_v);
        int nxt = cur ^ 1;
        edge_kernel<<<BB*(NN/WPB), WPB*32>>>(l, cur, nxt, (l == NL-1) ? 1 : 0,
                                             We1, We2, be2, Wx, Wh1, vs, out);
        cur = nxt;
    }
}

// round 6
// speedup vs baseline: 1.1772x; 1.1772x over previous
#include <cuda_runtime.h>

typedef unsigned long long u64;

#define BB 32
#define NN 256
#define NF 16
#define NL 3
#define NODES (BB*NN)
#define WPB 4   // warps (dst nodes) per block

// ping-pong state (static device allocs: allowed).
// Precomputed node terms are double-buffered by layer parity to avoid the
// cross-block race between epilogue writes (layer l+1) and tile reads (layer l).
__device__ float4 g_x[2][NODES];
__device__ float  g_h[2][NODES*NF];
__device__ u64    g_A2[2][NODES*(NF/2)];    // packed pairs: h_i @ We1[0:NF]
__device__ u64    g_Bjb2[2][NODES*(NF/2)];  // packed pairs: h_j @ We1[NF:2NF] + be1
__device__ float  g_hWh[2][NODES*NF];       // h_j @ Wh1[0:NF] + bh1
__device__ float  g_hv[2][NODES];           // h_j @ W_v

// ---- packed fp32x2 helpers (sm_103a FFMA2 path, PTX-only) ----
__device__ __forceinline__ u64 pk(float lo, float hi) {
    u64 r; asm("mov.b64 %0, {%1,%2};" : "=l"(r) : "f"(lo), "f"(hi)); return r;
}
__device__ __forceinline__ float2 upk(u64 v) {
    float2 r; asm("mov.b64 {%0,%1}, %2;" : "=f"(r.x), "=f"(r.y) : "l"(v)); return r;
}
__device__ __forceinline__ void f2fma_acc(u64& d, u64 a, u64 b) {
    asm("fma.rn.f32x2 %0, %1, %2, %0;" : "+l"(d) : "l"(a), "l"(b));
}
__device__ __forceinline__ u64 f2fma(u64 a, u64 b, u64 c) {
    u64 d; asm("fma.rn.f32x2 %0, %1, %2, %3;" : "=l"(d) : "l"(a), "l"(b), "l"(c)); return d;
}
__device__ __forceinline__ u64 f2add(u64 a, u64 b) {
    u64 d; asm("add.rn.f32x2 %0, %1, %2;" : "=l"(d) : "l"(a), "l"(b)); return d;
}

// init: node features h from charges, plus layer-0 node-side precompute (buffer 0)
__global__ void init_kernel(const float* __restrict__ xs,
                            const float* __restrict__ charges,
                            const float* __restrict__ W_in,
                            const float* __restrict__ b_in,
                            const float* __restrict__ W_v,
                            const float* __restrict__ We1,
                            const float* __restrict__ be1,
                            const float* __restrict__ Wh1,
                            const float* __restrict__ bh1) {
    int gid = blockIdx.x * blockDim.x + threadIdx.x;
    int node = gid >> 4;
    int k = gid & 15;
    if (node >= NODES) return;
    float c = charges[node];
    float h[NF];
    #pragma unroll
    for (int f = 0; f < NF; f++) {
        float v = fmaf(c, W_in[f], b_in[f]);
        h[f] = v > 0.f ? v : 0.f;
    }
    g_h[0][node*NF + k] = h[k];
    float a = 0.f, bb = 0.f, hw = 0.f;
    #pragma unroll
    for (int f = 0; f < NF; f++) {
        a  = fmaf(h[f], We1[f*NF + k],      a);
        bb = fmaf(h[f], We1[(NF+f)*NF + k], bb);
        hw = fmaf(h[f], Wh1[f*NF + k],      hw);
    }
    ((float*)g_A2[0])[node*NF + k]   = a;
    ((float*)g_Bjb2[0])[node*NF + k] = bb + be1[k];
    g_hWh[0][node*NF + k] = hw + bh1[k];
    if (k == 0) {
        float hv = 0.f;
        #pragma unroll
        for (int f = 0; f < NF; f++) hv = fmaf(h[f], W_v[f], hv);
        g_hv[0][node] = hv;
        float4 x;
        x.x = xs[node*3 + 0]; x.y = xs[node*3 + 1]; x.z = xs[node*3 + 2]; x.w = 0.f;
        g_x[0][node] = x;
    }
}

__global__ void __launch_bounds__(WPB*32)
edge_kernel(int l, int cur, int nxt, int last,
            const float* __restrict__ We1,
            const float* __restrict__ be1,
            const float* __restrict__ We2,
            const float* __restrict__ be2,
            const float* __restrict__ Wx,
            const float* __restrict__ Wh1,
            const float* __restrict__ bh1,
            const float* __restrict__ W_v,
            const float* __restrict__ vs,
            float* __restrict__ out) {
    __shared__ u64        sAT[8*NN];      // [q*NN + i]: packed (A[i][2q],A[i][2q+1]); LDS.64 conflict-free
    __shared__ float4     sX[NN];
    __shared__ ulonglong2 sWe2v[NF*4];    // row f at [f*4..f*4+3]: 16B -> 2 packed pairs each
    __shared__ float      sWh1b[NF*NF];   // Wh1 m_agg half [f][k]
    __shared__ float      sHn[WPB*NF];

    int tid  = threadIdx.x;
    int lane = tid & 31;
    int warp = tid >> 5;
    int b     = blockIdx.x >> 6;          // NN/WPB = 64 blocks per batch
    int jbase = (blockIdx.x & 63) * WPB;
    int nbase = b * NN;

    int pc = l & 1;        // precompute buffer for this layer
    int pn = pc ^ 1;       // precompute buffer for next layer

    // cooperative tile loads (coalesced gmem, scattered smem)
    for (int idx = tid; idx < NN*8; idx += WPB*32) {
        int i = idx >> 3, q = idx & 7;
        sAT[q*NN + i] = g_A2[pc][(nbase + i)*8 + q];
    }
    for (int i = tid; i < NN; i += WPB*32) sX[i] = g_x[cur][nbase + i];
    if (tid < NF*4) sWe2v[tid] = ((const ulonglong2*)We2)[l*(NF*NF/4) + tid];
    for (int idx = tid; idx < NF*NF; idx += WPB*32) {
        int f = idx >> 4, k = idx & 15;
        sWh1b[idx] = Wh1[l*(2*NF)*NF + (NF + f)*NF + k];
    }
    __syncthreads();

    int j = jbase + warp;
    int node = nbase + j;

    // per-warp packed constants
    u64 Bjb2[8], wr2[8], wxv2[8], bev2[8];
    const u64* wrp = (const u64*)We1 + (l*(2*NF+1)*NF + 2*NF*NF)/2;  // r2 row of We1
    #pragma unroll
    for (int q = 0; q < 8; q++) {
        Bjb2[q] = g_Bjb2[pc][node*8 + q];
        wr2[q]  = wrp[q];
        wxv2[q] = ((const u64*)Wx)[l*8 + q];
        bev2[q] = ((const u64*)be2)[l*8 + q];
    }
    float4 xj = sX[j];

    u64 magg2[8];
    #pragma unroll
    for (int q = 0; q < 8; q++) magg2[q] = 0ull;   // bits of (0.f,0.f)
    float ax = 0.f, ay = 0.f, az = 0.f;

    for (int it = 0; it < NN/32; it++) {
        int i = it*32 + lane;
        float4 xi = sX[i];
        float dx = xj.x - xi.x;
        float dy = xj.y - xi.y;
        float dz = xj.z - xi.z;
        float r2 = fmaf(dx, dx, fmaf(dy, dy, dz*dz));
        u64 r22 = pk(r2, r2);

        // t = relu(A_i + B_j + r2*wr)  (packed)
        float t[NF];
        #pragma unroll
        for (int q = 0; q < 8; q++) {
            u64 ab = f2add(sAT[q*NN + i], Bjb2[q]);
            float2 tv = upk(f2fma(r22, wr2[q], ab));
            t[2*q]   = fmaxf(tv.x, 0.f);
            t[2*q+1] = fmaxf(tv.y, 0.f);
        }

        // m = t @ We2 + be2   (128 FFMA2 instead of 256 FFMA)
        u64 m2[8];
        #pragma unroll
        for (int q = 0; q < 8; q++) m2[q] = bev2[q];
        #pragma unroll
        for (int f = 0; f < NF; f++) {
            u64 tf2 = pk(t[f], t[f]);
            ulonglong2 wa = sWe2v[f*4 + 0];
            ulonglong2 wb = sWe2v[f*4 + 1];
            ulonglong2 wc = sWe2v[f*4 + 2];
            ulonglong2 wd = sWe2v[f*4 + 3];
            f2fma_acc(m2[0], tf2, wa.x); f2fma_acc(m2[1], tf2, wa.y);
            f2fma_acc(m2[2], tf2, wb.x); f2fma_acc(m2[3], tf2, wb.y);
            f2fma_acc(m2[4], tf2, wc.x); f2fma_acc(m2[5], tf2, wc.y);
            f2fma_acc(m2[6], tf2, wd.x); f2fma_acc(m2[7], tf2, wd.y);
        }

        // relu, w = m·Wx (self edge harmless: dx=dy=dz=0), magg masked
        float maskf = (i == j) ? 0.f : 1.f;
        u64 mask2 = pk(maskf, maskf);
        u64 wacc = 0ull;
        #pragma unroll
        for (int q = 0; q < 8; q++) {
            float2 mv = upk(m2[q]);
            u64 mk2 = pk(fmaxf(mv.x, 0.f), fmaxf(mv.y, 0.f));
            f2fma_acc(wacc, mk2, wxv2[q]);
            f2fma_acc(magg2[q], mk2, mask2);
        }
        float2 wv = upk(wacc);
        float w = wv.x + wv.y;
        ax = fmaf(dx, w, ax);
        ay = fmaf(dy, w, ay);
        az = fmaf(dz, w, az);
    }

    // warp butterfly reductions (packed pairs reduce two features per shuffle pair)
    #pragma unroll
    for (int q = 0; q < 8; q++) {
        #pragma unroll
        for (int off = 16; off; off >>= 1)
            magg2[q] = f2add(magg2[q], __shfl_xor_sync(0xffffffffu, magg2[q], off));
    }
    #pragma unroll
    for (int off = 16; off; off >>= 1) {
        ax += __shfl_xor_sync(0xffffffffu, ax, off);
        ay += __shfl_xor_sync(0xffffffffu, ay, off);
        az += __shfl_xor_sync(0xffffffffu, az, off);
    }

    if (lane == 0) {
        float hv = g_hv[pc][node];
        const float inv = 1.f / (NN - 1);
        float ox = xj.x + ax*inv + vs[node*3 + 0]*hv;
        float oy = xj.y + ay*inv + vs[node*3 + 1]*hv;
        float oz = xj.z + az*inv + vs[node*3 + 2]*hv;
        if (last) {
            out[node*3 + 0] = ox;
            out[node*3 + 1] = oy;
            out[node*3 + 2] = oz;
        } else {
            g_x[nxt][node] = make_float4(ox, oy, oz, 0.f);
        }
    }

    if (!last) {
        // h update
        float maggv[NF];
        #pragma unroll
        for (int q = 0; q < 8; q++) {
            float2 v = upk(magg2[q]);
            maggv[2*q] = v.x; maggv[2*q+1] = v.y;
        }
        if (lane < NF) {
            float g = g_hWh[pc][node*NF + lane];
            #pragma unroll
            for (int f = 0; f < NF; f++) g = fmaf(maggv[f], sWh1b[f*NF + lane], g);
            float hn = g_h[cur][node*NF + lane] + (g > 0.f ? g : 0.f);
            g_h[nxt][node*NF + lane] = hn;
            sHn[warp*NF + lane] = hn;
        }
        __syncwarp();
        // fused next-layer node-side precompute — writes go to the OTHER buffer (pn),
        // so no block in this launch can observe them.
        int l1 = l + 1;
        const float* we1n = We1 + l1*(2*NF+1)*NF;
        const float* wh1n = Wh1 + l1*(2*NF)*NF;
        if (lane < NF) {
            float a = 0.f, bb = 0.f, hw = 0.f;
            #pragma unroll
            for (int f = 0; f < NF; f++) {
                float hf = sHn[warp*NF + f];
                a  = fmaf(hf, we1n[f*NF + lane],      a);
                bb = fmaf(hf, we1n[(NF+f)*NF + lane], bb);
                hw = fmaf(hf, wh1n[f*NF + lane],      hw);
            }
            ((float*)g_A2[pn])[node*NF + lane]   = a;
            ((float*)g_Bjb2[pn])[node*NF + lane] = bb + be1[l1*NF + lane];
            g_hWh[pn][node*NF + lane] = hw + bh1[l1*NF + lane];
        } else if (lane == NF) {
            float hv = 0.f;
            #pragma unroll
            for (int f = 0; f < NF; f++) hv = fmaf(sHn[warp*NF + f], W_v[l1*NF + f], hv);
            g_hv[pn][node] = hv;
        }
    }
}

extern "C" void kernel_launch(void* const* d_in, const int* in_sizes, int n_in,
                              void* d_out, int out_size) {
    const float* xs      = (const float*)d_in[0];
    const float* vs      = (const float*)d_in[1];
    const float* charges = (const float*)d_in[2];
    const float* W_in    = (const float*)d_in[3];
    const float* b_in    = (const float*)d_in[4];
    const float* W_v     = (const float*)d_in[5];
    const float* We1     = (const float*)d_in[6];
    const float* be1     = (const float*)d_in[7];
    const float* We2     = (const float*)d_in[8];
    const float* be2     = (const float*)d_in[9];
    const float* Wx      = (const float*)d_in[10];
    const float* Wh1     = (const float*)d_in[11];
    const float* bh1     = (const float*)d_in[12];
    float* out = (float*)d_out;

    init_kernel<<<(NODES*NF + 255)/256, 256>>>(xs, charges, W_in, b_in,
                                               W_v, We1, be1, Wh1, bh1);
    int cur = 0;
    for (int l = 0; l < NL; l++) {
        int nxt = cur ^ 1;
        edge_kernel<<<BB*(NN/WPB), WPB*32>>>(l, cur, nxt, (l == NL-1) ? 1 : 0,
                                             We1, be1, We2, be2, Wx, Wh1, bh1, W_v,
                                             vs, out);
        cur = nxt;
    }
}